// round 3
// baseline (speedup 1.0000x reference)
#include <cuda_runtime.h>
#include <cuda_fp16.h>
#include <cstdint>

// ============================================================================
// BinaryLinear: y = x @ sign(W)^T + sign(b)
//   x [8192,4096] f32, W [4096,4096] f32, b [4096] f32 -> y [8192,4096] f32
// Base-sm_103-compatible path (tcgen05 rejected by the harness's PTX target):
//   fp32 -> fp16 convert pre-pass, then mma.sync.m16n8k16 (HMMA) GEMM with
//   cp.async 4-stage pipeline, fp32 accumulation, fused sign(bias) epilogue.
// ============================================================================

#define TOKENS 8192
#define KDIM   4096
#define NDIM   4096

#define BM 128
#define BN 128
#define BK 64
#define NKIT   (KDIM / BK)          // 64
#define TILES_N (NDIM / BN)         // 32
#define TILES_M (TOKENS / BM)       // 64

#define STAGES 4
#define A_STAGE_BYTES (BM * BK * 2)           // 16384
#define STAGE_BYTES   (2 * A_STAGE_BYTES)     // 32768 (A + B)
#define SMEM_TOTAL    (STAGES * STAGE_BYTES)  // 131072

__device__ __half g_xh[(size_t)TOKENS * KDIM];   // 64 MB scratch
__device__ __half g_wh[(size_t)NDIM * KDIM];     // 32 MB scratch

// ---------------------------------------------------------------------------
// helpers
// ---------------------------------------------------------------------------
__device__ __forceinline__ uint32_t smem_u32(const void* p) {
    uint32_t a;
    asm("{ .reg .u64 t; cvta.to.shared.u64 t, %1; cvt.u32.u64 %0, t; }"
        : "=r"(a) : "l"(p));
    return a;
}

__device__ __forceinline__ void cp16(uint32_t saddr, const void* gaddr) {
    asm volatile("cp.async.cg.shared.global [%0], [%1], 16;"
                 :: "r"(saddr), "l"(gaddr));
}

__device__ __forceinline__ void ldsm4(uint32_t* r, uint32_t addr) {
    asm volatile("ldmatrix.sync.aligned.m8n8.x4.shared.b16 {%0,%1,%2,%3}, [%4];"
                 : "=r"(r[0]), "=r"(r[1]), "=r"(r[2]), "=r"(r[3]) : "r"(addr));
}

__device__ __forceinline__ void mma16816(float* d, const uint32_t* a,
                                         uint32_t b0, uint32_t b1) {
    asm volatile(
        "mma.sync.aligned.m16n8k16.row.col.f32.f16.f16.f32 "
        "{%0,%1,%2,%3}, {%4,%5,%6,%7}, {%8,%9}, {%0,%1,%2,%3};"
        : "+f"(d[0]), "+f"(d[1]), "+f"(d[2]), "+f"(d[3])
        : "r"(a[0]), "r"(a[1]), "r"(a[2]), "r"(a[3]), "r"(b0), "r"(b1));
}

// SW128-style swizzle shared by producer and consumer:
//   byte offset within tile = row*128 + (((row&7) ^ k8) << 4)
__device__ __forceinline__ void load_stage(uint32_t sb, int buf,
                                           const __half* Ag, const __half* Bg,
                                           int kofs, int tid) {
    uint32_t bufA = sb + (uint32_t)buf * STAGE_BYTES;
    uint32_t bufB = bufA + A_STAGE_BYTES;
    #pragma unroll
    for (int it = 0; it < 4; it++) {
        int c = tid + it * 256;          // 0..1023
        int row = c >> 3;
        int kc = c & 7;                  // 16B chunk within 128B row
        uint32_t sw = (uint32_t)row * 128 + ((uint32_t)((row & 7) ^ kc) << 4);
        const __half* ga = Ag + (size_t)row * KDIM + kofs + kc * 8;
        const __half* gb = Bg + (size_t)row * KDIM + kofs + kc * 8;
        cp16(bufA + sw, ga);
        cp16(bufB + sw, gb);
    }
}

// ---------------------------------------------------------------------------
// Pre-pass: fp32 -> fp16 conversions
// ---------------------------------------------------------------------------
__global__ void __launch_bounds__(256) k_cvt_x(const float4* __restrict__ x) {
    int i = blockIdx.x * 256 + threadIdx.x;
    float4 v = x[i];
    __half2 h0 = __floats2half2_rn(v.x, v.y);
    __half2 h1 = __floats2half2_rn(v.z, v.w);
    uint2 o;
    o.x = *reinterpret_cast<uint32_t*>(&h0);
    o.y = *reinterpret_cast<uint32_t*>(&h1);
    reinterpret_cast<uint2*>(g_xh)[i] = o;
}

__global__ void __launch_bounds__(256) k_cvt_w(const float4* __restrict__ w) {
    int i = blockIdx.x * 256 + threadIdx.x;
    float4 v = w[i];
    __half2 h0 = __floats2half2_rn(v.x >= 0.f ? 1.f : -1.f,
                                   v.y >= 0.f ? 1.f : -1.f);
    __half2 h1 = __floats2half2_rn(v.z >= 0.f ? 1.f : -1.f,
                                   v.w >= 0.f ? 1.f : -1.f);
    uint2 o;
    o.x = *reinterpret_cast<uint32_t*>(&h0);
    o.y = *reinterpret_cast<uint32_t*>(&h1);
    reinterpret_cast<uint2*>(g_wh)[i] = o;
}

// ---------------------------------------------------------------------------
// HMMA GEMM: 128x128 CTA tile, 8 warps (2x4), warp tile 64x32,
// mma.m16n8k16 fp16->fp32, 4-stage cp.async pipeline.
// ---------------------------------------------------------------------------
__global__ void __launch_bounds__(256) binlin_gemm(const float* __restrict__ bias,
                                                   float* __restrict__ out) {
    extern __shared__ char smem[];
    const uint32_t sb = smem_u32(smem);
    const int tid = threadIdx.x;
    const int wid = tid >> 5;
    const int lid = tid & 31;

    const int tileN = blockIdx.x % TILES_N;   // consecutive bids share tileM:
    const int tileM = blockIdx.x / TILES_N;   // A reuse + full W resident in L2
    const int m0 = tileM * BM;
    const int n0 = tileN * BN;

    const __half* Ag = g_xh + (size_t)m0 * KDIM;
    const __half* Bg = g_wh + (size_t)n0 * KDIM;

    const int warpM = wid >> 2;               // 0..1
    const int warpN = wid & 3;                // 0..3

    // ldmatrix lane address components
    const int rowa = warpM * 64 + (lid & 15);
    const int ka   = lid >> 4;                // A: k8-half select
    const int rowb = warpN * 32 + (lid & 7) + ((lid >> 4) << 3);
    const int kb   = (lid >> 3) & 1;          // B: k8-half select
    const uint32_t offA0 = (uint32_t)rowa * 128;
    const uint32_t offB0 = (uint32_t)rowb * 128;
    const int ra7 = rowa & 7;
    const int rb7 = rowb & 7;

    float acc[4][4][4];
    #pragma unroll
    for (int i = 0; i < 4; i++)
        #pragma unroll
        for (int j = 0; j < 4; j++)
            #pragma unroll
            for (int r = 0; r < 4; r++) acc[i][j][r] = 0.f;

    // pipeline prologue: stages 0..STAGES-2
    #pragma unroll
    for (int s = 0; s < STAGES - 1; s++) {
        load_stage(sb, s, Ag, Bg, s * BK, tid);
        asm volatile("cp.async.commit_group;" ::: "memory");
    }

    for (int kt = 0; kt < NKIT; kt++) {
        asm volatile("cp.async.wait_group 2;" ::: "memory");
        __syncthreads();

        const int knext = kt + STAGES - 1;
        if (knext < NKIT)
            load_stage(sb, knext & (STAGES - 1), Ag, Bg, knext * BK, tid);
        asm volatile("cp.async.commit_group;" ::: "memory");

        const uint32_t bufA = sb + (uint32_t)(kt & (STAGES - 1)) * STAGE_BYTES;
        const uint32_t bufB = bufA + A_STAGE_BYTES;

        #pragma unroll
        for (int ks = 0; ks < 4; ks++) {
            uint32_t a_r[4][4], b_r[2][4];
            #pragma unroll
            for (int mi = 0; mi < 4; mi++) {
                uint32_t ad = bufA + offA0 + (uint32_t)(mi * 16 * 128)
                            + ((uint32_t)(ra7 ^ (ks * 2 + ka)) << 4);
                ldsm4(a_r[mi], ad);
            }
            #pragma unroll
            for (int nj = 0; nj < 2; nj++) {
                uint32_t bd = bufB + offB0 + (uint32_t)(nj * 16 * 128)
                            + ((uint32_t)(rb7 ^ (ks * 2 + kb)) << 4);
                ldsm4(b_r[nj], bd);
            }
            #pragma unroll
            for (int mi = 0; mi < 4; mi++)
                #pragma unroll
                for (int n8 = 0; n8 < 4; n8++)
                    mma16816(acc[mi][n8], a_r[mi],
                             b_r[n8 >> 1][(n8 & 1) * 2],
                             b_r[n8 >> 1][(n8 & 1) * 2 + 1]);
        }
    }

    // epilogue: fused sign(bias), float2 stores
    const int m0w = m0 + warpM * 64;
    const int n0w = n0 + warpN * 32;
    const int rr = lid >> 2;
    const int cq = (lid & 3) * 2;

    float sb0[4], sb1[4];
    #pragma unroll
    for (int n8 = 0; n8 < 4; n8++) {
        int c = n0w + n8 * 8 + cq;
        sb0[n8] = bias[c]     >= 0.f ? 1.f : -1.f;
        sb1[n8] = bias[c + 1] >= 0.f ? 1.f : -1.f;
    }

    #pragma unroll
    for (int mi = 0; mi < 4; mi++) {
        const int r1 = m0w + mi * 16 + rr;
        #pragma unroll
        for (int n8 = 0; n8 < 4; n8++) {
            const int c = n0w + n8 * 8 + cq;
            float2 v1, v2;
            v1.x = acc[mi][n8][0] + sb0[n8];
            v1.y = acc[mi][n8][1] + sb1[n8];
            v2.x = acc[mi][n8][2] + sb0[n8];
            v2.y = acc[mi][n8][3] + sb1[n8];
            *reinterpret_cast<float2*>(out + (size_t)r1 * NDIM + c) = v1;
            *reinterpret_cast<float2*>(out + (size_t)(r1 + 8) * NDIM + c) = v2;
        }
    }
}

// ---------------------------------------------------------------------------
// Entry point
// ---------------------------------------------------------------------------
extern "C" void kernel_launch(void* const* d_in, const int* in_sizes, int n_in,
                              void* d_out, int out_size) {
    const float* x    = (const float*)d_in[0];
    const float* w    = (const float*)d_in[1];
    const float* bias = (const float*)d_in[2];
    float* out = (float*)d_out;
    (void)in_sizes; (void)n_in; (void)out_size;

    k_cvt_x<<<(TOKENS * KDIM / 4) / 256, 256>>>((const float4*)x);
    k_cvt_w<<<(NDIM * KDIM / 4) / 256, 256>>>((const float4*)w);

    cudaFuncSetAttribute(binlin_gemm,
                         cudaFuncAttributeMaxDynamicSharedMemorySize, SMEM_TOTAL);
    binlin_gemm<<<TILES_M * TILES_N, 256, SMEM_TOTAL>>>(bias, out);
}

// round 4
// speedup vs baseline: 1.2575x; 1.2575x over previous
#include <cuda_runtime.h>
#include <cuda_fp16.h>
#include <cstdint>

// ============================================================================
// BinaryLinear: y = x @ sign(W)^T + sign(b)
//   x [8192,4096] f32, W [4096,4096] f32, b [4096] f32 -> y [8192,4096] f32
// fp32 -> fp16 convert pre-pass, then mma.sync.m16n8k16 (HMMA) GEMM,
// 3-stage cp.async pipeline, 2 CTAs/SM, fp32 accum, fused sign(bias) epilogue.
// ============================================================================

#define TOKENS 8192
#define KDIM   4096
#define NDIM   4096

#define BM 128
#define BN 128
#define BK 64
#define NKIT   (KDIM / BK)          // 64
#define TILES_N (NDIM / BN)         // 32
#define TILES_M (TOKENS / BM)       // 64

#define STAGES 3
#define A_STAGE_BYTES (BM * BK * 2)           // 16384
#define STAGE_BYTES   (2 * A_STAGE_BYTES)     // 32768 (A + B)
#define SMEM_TOTAL    (STAGES * STAGE_BYTES)  // 98304 -> 2 CTAs/SM

__device__ __half g_xh[(size_t)TOKENS * KDIM];   // 64 MB scratch
__device__ __half g_wh[(size_t)NDIM * KDIM];     // 32 MB scratch

// ---------------------------------------------------------------------------
// helpers
// ---------------------------------------------------------------------------
__device__ __forceinline__ uint32_t smem_u32(const void* p) {
    uint32_t a;
    asm("{ .reg .u64 t; cvta.to.shared.u64 t, %1; cvt.u32.u64 %0, t; }"
        : "=r"(a) : "l"(p));
    return a;
}

__device__ __forceinline__ void cp16(uint32_t saddr, const void* gaddr) {
    asm volatile("cp.async.cg.shared.global [%0], [%1], 16;"
                 :: "r"(saddr), "l"(gaddr));
}

__device__ __forceinline__ void ldsm4(uint32_t* r, uint32_t addr) {
    asm volatile("ldmatrix.sync.aligned.m8n8.x4.shared.b16 {%0,%1,%2,%3}, [%4];"
                 : "=r"(r[0]), "=r"(r[1]), "=r"(r[2]), "=r"(r[3]) : "r"(addr));
}

__device__ __forceinline__ void mma16816(float* d, const uint32_t* a,
                                         uint32_t b0, uint32_t b1) {
    asm volatile(
        "mma.sync.aligned.m16n8k16.row.col.f32.f16.f16.f32 "
        "{%0,%1,%2,%3}, {%4,%5,%6,%7}, {%8,%9}, {%0,%1,%2,%3};"
        : "+f"(d[0]), "+f"(d[1]), "+f"(d[2]), "+f"(d[3])
        : "r"(a[0]), "r"(a[1]), "r"(a[2]), "r"(a[3]), "r"(b0), "r"(b1));
}

// SW128-style swizzle shared by producer and consumer:
//   byte offset within tile = row*128 + (((row&7) ^ k8chunk) << 4)
__device__ __forceinline__ void load_stage(uint32_t sb, int buf,
                                           const __half* Ag, const __half* Bg,
                                           int kofs, int tid) {
    uint32_t bufA = sb + (uint32_t)buf * STAGE_BYTES;
    uint32_t bufB = bufA + A_STAGE_BYTES;
    const int row0 = tid >> 3;
    const int kc = tid & 7;
    const uint32_t sw0 = (uint32_t)row0 * 128 + ((uint32_t)((row0 & 7) ^ kc) << 4);
    const __half* ga = Ag + (size_t)row0 * KDIM + kofs + kc * 8;
    const __half* gb = Bg + (size_t)row0 * KDIM + kofs + kc * 8;
    #pragma unroll
    for (int it = 0; it < 4; it++) {
        // rows advance by 32 per it (32 % 8 == 0 -> same swizzle xor term)
        uint32_t sw = sw0 + (uint32_t)it * 32 * 128;
        cp16(bufA + sw, ga + (size_t)it * 32 * KDIM);
        cp16(bufB + sw, gb + (size_t)it * 32 * KDIM);
    }
}

// ---------------------------------------------------------------------------
// Pre-pass: fp32 -> fp16 conversions
// ---------------------------------------------------------------------------
__global__ void __launch_bounds__(256) k_cvt_x(const float4* __restrict__ x) {
    int i = blockIdx.x * 256 + threadIdx.x;
    float4 v = x[i];
    __half2 h0 = __floats2half2_rn(v.x, v.y);
    __half2 h1 = __floats2half2_rn(v.z, v.w);
    uint2 o;
    o.x = *reinterpret_cast<uint32_t*>(&h0);
    o.y = *reinterpret_cast<uint32_t*>(&h1);
    reinterpret_cast<uint2*>(g_xh)[i] = o;
}

__global__ void __launch_bounds__(256) k_cvt_w(const float4* __restrict__ w) {
    int i = blockIdx.x * 256 + threadIdx.x;
    float4 v = w[i];
    __half2 h0 = __floats2half2_rn(v.x >= 0.f ? 1.f : -1.f,
                                   v.y >= 0.f ? 1.f : -1.f);
    __half2 h1 = __floats2half2_rn(v.z >= 0.f ? 1.f : -1.f,
                                   v.w >= 0.f ? 1.f : -1.f);
    uint2 o;
    o.x = *reinterpret_cast<uint32_t*>(&h0);
    o.y = *reinterpret_cast<uint32_t*>(&h1);
    reinterpret_cast<uint2*>(g_wh)[i] = o;
}

// ---------------------------------------------------------------------------
// HMMA GEMM: 128x128 CTA tile, 8 warps (2x4), warp tile 64x32,
// mma.m16n8k16 fp16->fp32, 3-stage cp.async pipeline, 2 CTAs/SM.
// ---------------------------------------------------------------------------
__global__ void __launch_bounds__(256, 2) binlin_gemm(const float* __restrict__ bias,
                                                      float* __restrict__ out) {
    extern __shared__ char smem[];
    const uint32_t sb = smem_u32(smem);
    const int tid = threadIdx.x;
    const int wid = tid >> 5;
    const int lid = tid & 31;

    const int tileN = blockIdx.x % TILES_N;   // consecutive bids share tileM:
    const int tileM = blockIdx.x / TILES_N;   // A reuse + W resident in L2
    const int m0 = tileM * BM;
    const int n0 = tileN * BN;

    const __half* Ag = g_xh + (size_t)m0 * KDIM;
    const __half* Bg = g_wh + (size_t)n0 * KDIM;

    const int warpM = wid >> 2;               // 0..1
    const int warpN = wid & 3;                // 0..3

    // ldmatrix lane address components
    const int rowa = warpM * 64 + (lid & 15);
    const int ka   = lid >> 4;                // A: k8-half select
    const int rowb = warpN * 32 + (lid & 7) + ((lid >> 4) << 3);
    const int kb   = (lid >> 3) & 1;          // B: k8-half select
    const uint32_t offA0 = (uint32_t)rowa * 128;
    const uint32_t offB0 = (uint32_t)rowb * 128;
    const int ra7 = rowa & 7;
    const int rb7 = rowb & 7;

    float acc[4][4][4];
    #pragma unroll
    for (int i = 0; i < 4; i++)
        #pragma unroll
        for (int j = 0; j < 4; j++)
            #pragma unroll
            for (int r = 0; r < 4; r++) acc[i][j][r] = 0.f;

    // pipeline prologue: stages 0..STAGES-2
    #pragma unroll
    for (int s = 0; s < STAGES - 1; s++) {
        load_stage(sb, s, Ag, Bg, s * BK, tid);
        asm volatile("cp.async.commit_group;" ::: "memory");
    }

    int buf_rd = 0;              // buffer consumed this iteration
    int buf_ld = STAGES - 1;     // buffer filled this iteration

    for (int kt = 0; kt < NKIT; kt++) {
        asm volatile("cp.async.wait_group %0;" :: "n"(STAGES - 2) : "memory");
        __syncthreads();

        const int knext = kt + STAGES - 1;
        if (knext < NKIT)
            load_stage(sb, buf_ld, Ag, Bg, knext * BK, tid);
        asm volatile("cp.async.commit_group;" ::: "memory");
        if (++buf_ld == STAGES) buf_ld = 0;

        const uint32_t bufA = sb + (uint32_t)buf_rd * STAGE_BYTES;
        const uint32_t bufB = bufA + A_STAGE_BYTES;
        if (++buf_rd == STAGES) buf_rd = 0;

        #pragma unroll
        for (int ks = 0; ks < 4; ks++) {
            uint32_t a_r[4][4], b_r[2][4];
            #pragma unroll
            for (int mi = 0; mi < 4; mi++) {
                uint32_t ad = bufA + offA0 + (uint32_t)(mi * 16 * 128)
                            + ((uint32_t)(ra7 ^ (ks * 2 + ka)) << 4);
                ldsm4(a_r[mi], ad);
            }
            #pragma unroll
            for (int nj = 0; nj < 2; nj++) {
                uint32_t bd = bufB + offB0 + (uint32_t)(nj * 16 * 128)
                            + ((uint32_t)(rb7 ^ (ks * 2 + kb)) << 4);
                ldsm4(b_r[nj], bd);
            }
            #pragma unroll
            for (int mi = 0; mi < 4; mi++)
                #pragma unroll
                for (int n8 = 0; n8 < 4; n8++)
                    mma16816(acc[mi][n8], a_r[mi],
                             b_r[n8 >> 1][(n8 & 1) * 2],
                             b_r[n8 >> 1][(n8 & 1) * 2 + 1]);
        }
    }

    // epilogue: fused sign(bias), float2 stores
    const int m0w = m0 + warpM * 64;
    const int n0w = n0 + warpN * 32;
    const int rr = lid >> 2;
    const int cq = (lid & 3) * 2;

    float sb0[4], sb1[4];
    #pragma unroll
    for (int n8 = 0; n8 < 4; n8++) {
        int c = n0w + n8 * 8 + cq;
        sb0[n8] = bias[c]     >= 0.f ? 1.f : -1.f;
        sb1[n8] = bias[c + 1] >= 0.f ? 1.f : -1.f;
    }

    #pragma unroll
    for (int mi = 0; mi < 4; mi++) {
        const int r1 = m0w + mi * 16 + rr;
        #pragma unroll
        for (int n8 = 0; n8 < 4; n8++) {
            const int c = n0w + n8 * 8 + cq;
            float2 v1, v2;
            v1.x = acc[mi][n8][0] + sb0[n8];
            v1.y = acc[mi][n8][1] + sb1[n8];
            v2.x = acc[mi][n8][2] + sb0[n8];
            v2.y = acc[mi][n8][3] + sb1[n8];
            *reinterpret_cast<float2*>(out + (size_t)r1 * NDIM + c) = v1;
            *reinterpret_cast<float2*>(out + (size_t)(r1 + 8) * NDIM + c) = v2;
        }
    }
}

// ---------------------------------------------------------------------------
// Entry point
// ---------------------------------------------------------------------------
extern "C" void kernel_launch(void* const* d_in, const int* in_sizes, int n_in,
                              void* d_out, int out_size) {
    const float* x    = (const float*)d_in[0];
    const float* w    = (const float*)d_in[1];
    const float* bias = (const float*)d_in[2];
    float* out = (float*)d_out;
    (void)in_sizes; (void)n_in; (void)out_size;

    k_cvt_x<<<(TOKENS * KDIM / 4) / 256, 256>>>((const float4*)x);
    k_cvt_w<<<(NDIM * KDIM / 4) / 256, 256>>>((const float4*)w);

    cudaFuncSetAttribute(binlin_gemm,
                         cudaFuncAttributeMaxDynamicSharedMemorySize, SMEM_TOTAL);
    binlin_gemm<<<TILES_M * TILES_N, 256, SMEM_TOTAL>>>(bias, out);
}

// round 5
// speedup vs baseline: 1.2619x; 1.0035x over previous
#include <cuda_runtime.h>
#include <cuda_fp16.h>
#include <cstdint>

// ============================================================================
// BinaryLinear: y = x @ sign(W)^T + sign(b)
//   x [8192,4096] f32, W [4096,4096] f32, b [4096] f32 -> y [8192,4096] f32
// fp32 -> fp16 convert pre-pass, then mma.sync.m16n8k16 (HMMA) GEMM:
// 256x128 CTA tile, 512 threads (16 warps, 4x4), warp tile 64x32,
// 4-stage cp.async pipeline (192KB smem), fp32 accum, fused sign(bias).
// ============================================================================

#define TOKENS 8192
#define KDIM   4096
#define NDIM   4096

#define BM 256
#define BN 128
#define BK 64
#define NKIT   (KDIM / BK)          // 64
#define TILES_N (NDIM / BN)         // 32
#define TILES_M (TOKENS / BM)       // 32

#define STAGES 4
#define A_STAGE_BYTES (BM * BK * 2)           // 32768
#define B_STAGE_BYTES (BN * BK * 2)           // 16384
#define STAGE_BYTES   (A_STAGE_BYTES + B_STAGE_BYTES)   // 49152
#define SMEM_TOTAL    (STAGES * STAGE_BYTES)  // 196608

__device__ __half g_xh[(size_t)TOKENS * KDIM];   // 64 MB scratch
__device__ __half g_wh[(size_t)NDIM * KDIM];     // 32 MB scratch

// ---------------------------------------------------------------------------
// helpers
// ---------------------------------------------------------------------------
__device__ __forceinline__ uint32_t smem_u32(const void* p) {
    uint32_t a;
    asm("{ .reg .u64 t; cvta.to.shared.u64 t, %1; cvt.u32.u64 %0, t; }"
        : "=r"(a) : "l"(p));
    return a;
}

__device__ __forceinline__ void cp16(uint32_t saddr, const void* gaddr) {
    asm volatile("cp.async.cg.shared.global [%0], [%1], 16;"
                 :: "r"(saddr), "l"(gaddr));
}

__device__ __forceinline__ void ldsm4(uint32_t* r, uint32_t addr) {
    asm volatile("ldmatrix.sync.aligned.m8n8.x4.shared.b16 {%0,%1,%2,%3}, [%4];"
                 : "=r"(r[0]), "=r"(r[1]), "=r"(r[2]), "=r"(r[3]) : "r"(addr));
}

__device__ __forceinline__ void mma16816(float* d, const uint32_t* a,
                                         uint32_t b0, uint32_t b1) {
    asm volatile(
        "mma.sync.aligned.m16n8k16.row.col.f32.f16.f16.f32 "
        "{%0,%1,%2,%3}, {%4,%5,%6,%7}, {%8,%9}, {%0,%1,%2,%3};"
        : "+f"(d[0]), "+f"(d[1]), "+f"(d[2]), "+f"(d[3])
        : "r"(a[0]), "r"(a[1]), "r"(a[2]), "r"(a[3]), "r"(b0), "r"(b1));
}

// SW128-style swizzle shared by producer and consumer:
//   byte offset within tile = row*128 + (((row&7) ^ k8chunk) << 4)
// Producer: 512 threads fill A (256 rows x 8 chunks = 2048 cp) and
// B (128 rows x 8 chunks = 1024 cp): 4 + 2 cp16 per thread.
__device__ __forceinline__ void load_stage(uint32_t sb, int buf,
                                           const __half* Ag, const __half* Bg,
                                           int kofs, int tid) {
    uint32_t bufA = sb + (uint32_t)buf * STAGE_BYTES;
    uint32_t bufB = bufA + A_STAGE_BYTES;
    const int row0 = tid >> 3;          // 0..63
    const int kc = tid & 7;
    const uint32_t sw0 = (uint32_t)row0 * 128 + ((uint32_t)((row0 & 7) ^ kc) << 4);
    const __half* ga = Ag + (size_t)row0 * KDIM + kofs + kc * 8;
    const __half* gb = Bg + (size_t)row0 * KDIM + kofs + kc * 8;
    #pragma unroll
    for (int it = 0; it < 4; it++) {    // A rows: row0 + 64*it
        uint32_t sw = sw0 + (uint32_t)it * 64 * 128;
        cp16(bufA + sw, ga + (size_t)it * 64 * KDIM);
    }
    #pragma unroll
    for (int it = 0; it < 2; it++) {    // B rows: row0 + 64*it
        uint32_t sw = sw0 + (uint32_t)it * 64 * 128;
        cp16(bufB + sw, gb + (size_t)it * 64 * KDIM);
    }
}

// ---------------------------------------------------------------------------
// Pre-pass: fp32 -> fp16 conversions
// ---------------------------------------------------------------------------
__global__ void __launch_bounds__(256) k_cvt_x(const float4* __restrict__ x) {
    int i = blockIdx.x * 256 + threadIdx.x;
    float4 v = x[i];
    __half2 h0 = __floats2half2_rn(v.x, v.y);
    __half2 h1 = __floats2half2_rn(v.z, v.w);
    uint2 o;
    o.x = *reinterpret_cast<uint32_t*>(&h0);
    o.y = *reinterpret_cast<uint32_t*>(&h1);
    reinterpret_cast<uint2*>(g_xh)[i] = o;
}

__global__ void __launch_bounds__(256) k_cvt_w(const float4* __restrict__ w) {
    int i = blockIdx.x * 256 + threadIdx.x;
    float4 v = w[i];
    __half2 h0 = __floats2half2_rn(v.x >= 0.f ? 1.f : -1.f,
                                   v.y >= 0.f ? 1.f : -1.f);
    __half2 h1 = __floats2half2_rn(v.z >= 0.f ? 1.f : -1.f,
                                   v.w >= 0.f ? 1.f : -1.f);
    uint2 o;
    o.x = *reinterpret_cast<uint32_t*>(&h0);
    o.y = *reinterpret_cast<uint32_t*>(&h1);
    reinterpret_cast<uint2*>(g_wh)[i] = o;
}

// ---------------------------------------------------------------------------
// HMMA GEMM
// ---------------------------------------------------------------------------
__global__ void __launch_bounds__(512, 1) binlin_gemm(const float* __restrict__ bias,
                                                      float* __restrict__ out) {
    extern __shared__ char smem[];
    const uint32_t sb = smem_u32(smem);
    const int tid = threadIdx.x;
    const int wid = tid >> 5;
    const int lid = tid & 31;

    const int tileN = blockIdx.x % TILES_N;   // consecutive bids share tileM:
    const int tileM = blockIdx.x / TILES_N;   // A reuse + W resident in L2
    const int m0 = tileM * BM;
    const int n0 = tileN * BN;

    const __half* Ag = g_xh + (size_t)m0 * KDIM;
    const __half* Bg = g_wh + (size_t)n0 * KDIM;

    const int warpM = wid >> 2;               // 0..3 -> 64-row slices
    const int warpN = wid & 3;                // 0..3 -> 32-col slices

    // ldmatrix lane address components
    const int rowa = warpM * 64 + (lid & 15);
    const int ka   = lid >> 4;                // A: k8-half select
    const int rowb = warpN * 32 + (lid & 7) + ((lid >> 4) << 3);
    const int kb   = (lid >> 3) & 1;          // B: k8-half select
    const uint32_t offA0 = (uint32_t)rowa * 128;
    const uint32_t offB0 = (uint32_t)rowb * 128;
    const int ra7 = rowa & 7;
    const int rb7 = rowb & 7;

    float acc[4][4][4];
    #pragma unroll
    for (int i = 0; i < 4; i++)
        #pragma unroll
        for (int j = 0; j < 4; j++)
            #pragma unroll
            for (int r = 0; r < 4; r++) acc[i][j][r] = 0.f;

    // pipeline prologue: stages 0..STAGES-2
    #pragma unroll
    for (int s = 0; s < STAGES - 1; s++) {
        load_stage(sb, s, Ag, Bg, s * BK, tid);
        asm volatile("cp.async.commit_group;" ::: "memory");
    }

    int buf_rd = 0;              // buffer consumed this iteration
    int buf_ld = STAGES - 1;     // buffer filled this iteration

    for (int kt = 0; kt < NKIT; kt++) {
        asm volatile("cp.async.wait_group %0;" :: "n"(STAGES - 2) : "memory");
        __syncthreads();

        const int knext = kt + STAGES - 1;
        if (knext < NKIT)
            load_stage(sb, buf_ld, Ag, Bg, knext * BK, tid);
        asm volatile("cp.async.commit_group;" ::: "memory");
        if (++buf_ld == STAGES) buf_ld = 0;

        const uint32_t bufA = sb + (uint32_t)buf_rd * STAGE_BYTES;
        const uint32_t bufB = bufA + A_STAGE_BYTES;
        if (++buf_rd == STAGES) buf_rd = 0;

        #pragma unroll
        for (int ks = 0; ks < 4; ks++) {
            uint32_t a_r[4][4], b_r[2][4];
            #pragma unroll
            for (int mi = 0; mi < 4; mi++) {
                uint32_t ad = bufA + offA0 + (uint32_t)(mi * 16 * 128)
                            + ((uint32_t)(ra7 ^ (ks * 2 + ka)) << 4);
                ldsm4(a_r[mi], ad);
            }
            #pragma unroll
            for (int nj = 0; nj < 2; nj++) {
                uint32_t bd = bufB + offB0 + (uint32_t)(nj * 16 * 128)
                            + ((uint32_t)(rb7 ^ (ks * 2 + kb)) << 4);
                ldsm4(b_r[nj], bd);
            }
            #pragma unroll
            for (int mi = 0; mi < 4; mi++)
                #pragma unroll
                for (int n8 = 0; n8 < 4; n8++)
                    mma16816(acc[mi][n8], a_r[mi],
                             b_r[n8 >> 1][(n8 & 1) * 2],
                             b_r[n8 >> 1][(n8 & 1) * 2 + 1]);
        }
    }

    // epilogue: fused sign(bias), float2 stores
    const int m0w = m0 + warpM * 64;
    const int n0w = n0 + warpN * 32;
    const int rr = lid >> 2;
    const int cq = (lid & 3) * 2;

    float sb0[4], sb1[4];
    #pragma unroll
    for (int n8 = 0; n8 < 4; n8++) {
        int c = n0w + n8 * 8 + cq;
        sb0[n8] = bias[c]     >= 0.f ? 1.f : -1.f;
        sb1[n8] = bias[c + 1] >= 0.f ? 1.f : -1.f;
    }

    #pragma unroll
    for (int mi = 0; mi < 4; mi++) {
        const int r1 = m0w + mi * 16 + rr;
        #pragma unroll
        for (int n8 = 0; n8 < 4; n8++) {
            const int c = n0w + n8 * 8 + cq;
            float2 v1, v2;
            v1.x = acc[mi][n8][0] + sb0[n8];
            v1.y = acc[mi][n8][1] + sb1[n8];
            v2.x = acc[mi][n8][2] + sb0[n8];
            v2.y = acc[mi][n8][3] + sb1[n8];
            *reinterpret_cast<float2*>(out + (size_t)r1 * NDIM + c) = v1;
            *reinterpret_cast<float2*>(out + (size_t)(r1 + 8) * NDIM + c) = v2;
        }
    }
}

// ---------------------------------------------------------------------------
// Entry point
// ---------------------------------------------------------------------------
extern "C" void kernel_launch(void* const* d_in, const int* in_sizes, int n_in,
                              void* d_out, int out_size) {
    const float* x    = (const float*)d_in[0];
    const float* w    = (const float*)d_in[1];
    const float* bias = (const float*)d_in[2];
    float* out = (float*)d_out;
    (void)in_sizes; (void)n_in; (void)out_size;

    k_cvt_x<<<(TOKENS * KDIM / 4) / 256, 256>>>((const float4*)x);
    k_cvt_w<<<(NDIM * KDIM / 4) / 256, 256>>>((const float4*)w);

    cudaFuncSetAttribute(binlin_gemm,
                         cudaFuncAttributeMaxDynamicSharedMemorySize, SMEM_TOTAL);
    binlin_gemm<<<TILES_M * TILES_N, 512, SMEM_TOTAL>>>(bias, out);
}

// round 6
// speedup vs baseline: 1.2894x; 1.0218x over previous
#include <cuda_runtime.h>
#include <cuda_fp16.h>
#include <cstdint>

// ============================================================================
// BinaryLinear: y = x @ sign(W)^T + sign(b)
//   x [8192,4096] f32, W [4096,4096] f32, b [4096] f32 -> y [8192,4096] f32
// fp32 -> fp16 convert pre-pass, then mma.sync.m16n8k16 (HMMA) GEMM:
// 256x128 CTA tile, 512 threads (16 warps, 4x4), warp tile 64x32,
// BK=128, 2-stage cp.async pipeline (192KB smem), fp32 accum, fused sign(bias).
// ============================================================================

#define TOKENS 8192
#define KDIM   4096
#define NDIM   4096

#define BM 256
#define BN 128
#define BK 128
#define NKIT   (KDIM / BK)          // 32
#define TILES_N (NDIM / BN)         // 32
#define TILES_M (TOKENS / BM)       // 32

#define STAGES 2
#define ROWB 256                               // smem row bytes (BK * 2)
#define A_STAGE_BYTES (BM * ROWB)              // 65536
#define B_STAGE_BYTES (BN * ROWB)              // 32768
#define STAGE_BYTES   (A_STAGE_BYTES + B_STAGE_BYTES)   // 98304
#define SMEM_TOTAL    (STAGES * STAGE_BYTES)   // 196608

__device__ __half g_xh[(size_t)TOKENS * KDIM];   // 64 MB scratch
__device__ __half g_wh[(size_t)NDIM * KDIM];     // 32 MB scratch

// ---------------------------------------------------------------------------
// helpers
// ---------------------------------------------------------------------------
__device__ __forceinline__ uint32_t smem_u32(const void* p) {
    uint32_t a;
    asm("{ .reg .u64 t; cvta.to.shared.u64 t, %1; cvt.u32.u64 %0, t; }"
        : "=r"(a) : "l"(p));
    return a;
}

__device__ __forceinline__ void cp16(uint32_t saddr, const void* gaddr) {
    asm volatile("cp.async.cg.shared.global [%0], [%1], 16;"
                 :: "r"(saddr), "l"(gaddr));
}

__device__ __forceinline__ void ldsm4(uint32_t* r, uint32_t addr) {
    asm volatile("ldmatrix.sync.aligned.m8n8.x4.shared.b16 {%0,%1,%2,%3}, [%4];"
                 : "=r"(r[0]), "=r"(r[1]), "=r"(r[2]), "=r"(r[3]) : "r"(addr));
}

__device__ __forceinline__ void mma16816(float* d, const uint32_t* a,
                                         uint32_t b0, uint32_t b1) {
    asm volatile(
        "mma.sync.aligned.m16n8k16.row.col.f32.f16.f16.f32 "
        "{%0,%1,%2,%3}, {%4,%5,%6,%7}, {%8,%9}, {%0,%1,%2,%3};"
        : "+f"(d[0]), "+f"(d[1]), "+f"(d[2]), "+f"(d[3])
        : "r"(a[0]), "r"(a[1]), "r"(a[2]), "r"(a[3]), "r"(b0), "r"(b1));
}

// Swizzle for 256B rows: 16 16B-chunks per row; chunk' = chunk ^ (row & 7)
// (XOR hits only low 3 chunk bits; bit 3 passes through). Conflict-free for
// both STS.128 fills and 8-row ldmatrix reads.
// Producer: 512 threads; A: 256 rows x 16 chunks = 4096 cp16 -> 8/thread;
// B: 128 rows x 16 chunks = 2048 -> 4/thread.
__device__ __forceinline__ void load_stage(uint32_t sb, int buf,
                                           const __half* Ag, const __half* Bg,
                                           int kofs, int tid) {
    uint32_t bufA = sb + (uint32_t)buf * STAGE_BYTES;
    uint32_t bufB = bufA + A_STAGE_BYTES;
    const int row0 = tid >> 4;          // 0..31
    const int kc = tid & 15;
    const uint32_t sw0 = (uint32_t)row0 * ROWB
                       + ((uint32_t)(kc ^ (row0 & 7)) << 4);
    const __half* ga = Ag + (size_t)row0 * KDIM + kofs + kc * 8;
    const __half* gb = Bg + (size_t)row0 * KDIM + kofs + kc * 8;
    #pragma unroll
    for (int it = 0; it < 8; it++) {    // A rows: row0 + 32*it (32%8==0)
        uint32_t sw = sw0 + (uint32_t)it * 32 * ROWB;
        cp16(bufA + sw, ga + (size_t)it * 32 * KDIM);
    }
    #pragma unroll
    for (int it = 0; it < 4; it++) {    // B rows: row0 + 32*it
        uint32_t sw = sw0 + (uint32_t)it * 32 * ROWB;
        cp16(bufB + sw, gb + (size_t)it * 32 * KDIM);
    }
}

// ---------------------------------------------------------------------------
// Pre-pass: fp32 -> fp16 conversions
// ---------------------------------------------------------------------------
__global__ void __launch_bounds__(256) k_cvt_x(const float4* __restrict__ x) {
    int i = blockIdx.x * 256 + threadIdx.x;
    float4 v = x[i];
    __half2 h0 = __floats2half2_rn(v.x, v.y);
    __half2 h1 = __floats2half2_rn(v.z, v.w);
    uint2 o;
    o.x = *reinterpret_cast<uint32_t*>(&h0);
    o.y = *reinterpret_cast<uint32_t*>(&h1);
    reinterpret_cast<uint2*>(g_xh)[i] = o;
}

__global__ void __launch_bounds__(256) k_cvt_w(const float4* __restrict__ w) {
    int i = blockIdx.x * 256 + threadIdx.x;
    float4 v = w[i];
    __half2 h0 = __floats2half2_rn(v.x >= 0.f ? 1.f : -1.f,
                                   v.y >= 0.f ? 1.f : -1.f);
    __half2 h1 = __floats2half2_rn(v.z >= 0.f ? 1.f : -1.f,
                                   v.w >= 0.f ? 1.f : -1.f);
    uint2 o;
    o.x = *reinterpret_cast<uint32_t*>(&h0);
    o.y = *reinterpret_cast<uint32_t*>(&h1);
    reinterpret_cast<uint2*>(g_wh)[i] = o;
}

// ---------------------------------------------------------------------------
// HMMA GEMM
// ---------------------------------------------------------------------------
__global__ void __launch_bounds__(512, 1) binlin_gemm(const float* __restrict__ bias,
                                                      float* __restrict__ out) {
    extern __shared__ char smem[];
    const uint32_t sb = smem_u32(smem);
    const int tid = threadIdx.x;
    const int wid = tid >> 5;
    const int lid = tid & 31;

    const int tileN = blockIdx.x % TILES_N;   // consecutive bids share tileM:
    const int tileM = blockIdx.x / TILES_N;   // A reuse + W resident in L2
    const int m0 = tileM * BM;
    const int n0 = tileN * BN;

    const __half* Ag = g_xh + (size_t)m0 * KDIM;
    const __half* Bg = g_wh + (size_t)n0 * KDIM;

    const int warpM = wid >> 2;               // 0..3 -> 64-row slices
    const int warpN = wid & 3;                // 0..3 -> 32-col slices

    // ldmatrix lane address components
    const int rowa = warpM * 64 + (lid & 15);
    const int ka   = lid >> 4;                // A: k8-half select
    const int rowb = warpN * 32 + (lid & 7) + ((lid >> 4) << 3);
    const int kb   = (lid >> 3) & 1;          // B: k8-half select
    const uint32_t offA0 = (uint32_t)rowa * ROWB;
    const uint32_t offB0 = (uint32_t)rowb * ROWB;
    const int ra7 = rowa & 7;
    const int rb7 = rowb & 7;

    float acc[4][4][4];
    #pragma unroll
    for (int i = 0; i < 4; i++)
        #pragma unroll
        for (int j = 0; j < 4; j++)
            #pragma unroll
            for (int r = 0; r < 4; r++) acc[i][j][r] = 0.f;

    // prologue: fill stage 0
    load_stage(sb, 0, Ag, Bg, 0, tid);
    asm volatile("cp.async.commit_group;" ::: "memory");

    int buf_rd = 0;
    int buf_ld = 1;

    for (int kt = 0; kt < NKIT; kt++) {
        asm volatile("cp.async.wait_group 0;" ::: "memory");
        __syncthreads();

        const int knext = kt + 1;
        if (knext < NKIT)
            load_stage(sb, buf_ld, Ag, Bg, knext * BK, tid);
        asm volatile("cp.async.commit_group;" ::: "memory");
        buf_ld ^= 1;

        const uint32_t bufA = sb + (uint32_t)buf_rd * STAGE_BYTES;
        const uint32_t bufB = bufA + A_STAGE_BYTES;
        buf_rd ^= 1;

        #pragma unroll
        for (int ks = 0; ks < 8; ks++) {
            uint32_t a_r[4][4], b_r[2][4];
            #pragma unroll
            for (int mi = 0; mi < 4; mi++) {
                uint32_t ad = bufA + offA0 + (uint32_t)(mi * 16 * ROWB)
                            + ((uint32_t)((ks * 2 + ka) ^ ra7) << 4);
                ldsm4(a_r[mi], ad);
            }
            #pragma unroll
            for (int nj = 0; nj < 2; nj++) {
                uint32_t bd = bufB + offB0 + (uint32_t)(nj * 16 * ROWB)
                            + ((uint32_t)((ks * 2 + kb) ^ rb7) << 4);
                ldsm4(b_r[nj], bd);
            }
            #pragma unroll
            for (int mi = 0; mi < 4; mi++)
                #pragma unroll
                for (int n8 = 0; n8 < 4; n8++)
                    mma16816(acc[mi][n8], a_r[mi],
                             b_r[n8 >> 1][(n8 & 1) * 2],
                             b_r[n8 >> 1][(n8 & 1) * 2 + 1]);
        }
    }

    // epilogue: fused sign(bias), float2 stores
    const int m0w = m0 + warpM * 64;
    const int n0w = n0 + warpN * 32;
    const int rr = lid >> 2;
    const int cq = (lid & 3) * 2;

    float sb0[4], sb1[4];
    #pragma unroll
    for (int n8 = 0; n8 < 4; n8++) {
        int c = n0w + n8 * 8 + cq;
        sb0[n8] = bias[c]     >= 0.f ? 1.f : -1.f;
        sb1[n8] = bias[c + 1] >= 0.f ? 1.f : -1.f;
    }

    #pragma unroll
    for (int mi = 0; mi < 4; mi++) {
        const int r1 = m0w + mi * 16 + rr;
        #pragma unroll
        for (int n8 = 0; n8 < 4; n8++) {
            const int c = n0w + n8 * 8 + cq;
            float2 v1, v2;
            v1.x = acc[mi][n8][0] + sb0[n8];
            v1.y = acc[mi][n8][1] + sb1[n8];
            v2.x = acc[mi][n8][2] + sb0[n8];
            v2.y = acc[mi][n8][3] + sb1[n8];
            *reinterpret_cast<float2*>(out + (size_t)r1 * NDIM + c) = v1;
            *reinterpret_cast<float2*>(out + (size_t)(r1 + 8) * NDIM + c) = v2;
        }
    }
}

// ---------------------------------------------------------------------------
// Entry point
// ---------------------------------------------------------------------------
extern "C" void kernel_launch(void* const* d_in, const int* in_sizes, int n_in,
                              void* d_out, int out_size) {
    const float* x    = (const float*)d_in[0];
    const float* w    = (const float*)d_in[1];
    const float* bias = (const float*)d_in[2];
    float* out = (float*)d_out;
    (void)in_sizes; (void)n_in; (void)out_size;

    k_cvt_x<<<(TOKENS * KDIM / 4) / 256, 256>>>((const float4*)x);
    k_cvt_w<<<(NDIM * KDIM / 4) / 256, 256>>>((const float4*)w);

    cudaFuncSetAttribute(binlin_gemm,
                         cudaFuncAttributeMaxDynamicSharedMemorySize, SMEM_TOTAL);
    binlin_gemm<<<TILES_M * TILES_N, 512, SMEM_TOTAL>>>(bias, out);
}